// round 1
// baseline (speedup 1.0000x reference)
#include <cuda_runtime.h>

#define BN   8
#define CN   64
#define HN   256
#define WN   256
#define HP   257
#define WP   257
#define HWN  (HN * WN)          // 65536
#define NPIX (HP * WP)          // 66049
#define NBLK 65                 // ceil(66049 / 1024)
#define LN_EPS 1e-5f
#define NEG_SLOPE 0.01f

// Scratch (static device allocations — allowed)
__device__ float g_cs[BN * HWN];        // channel sum            [8,256,256]
__device__ float g_xs[BN * NPIX];       // pooled channel sum     [8,257,257]
__device__ float g_y [BN * NPIX];       // pre-LN feature map     [8,257,257]
__device__ float g_part[BN * NBLK * 2]; // per-block (sum, sumsq)
__device__ float g_stats[BN * 2];       // per-image (mean, inv_std)

// ---------------------------------------------------------------------------
// 1) Channel sum: cs[b,h,w] = sum_c x[b,c,h,w].  float4 vectorized.
//    One thread per 4 pixels; 64 coalesced strided loads each.
// ---------------------------------------------------------------------------
__global__ void k_chansum(const float* __restrict__ x) {
    int t = blockIdx.x * blockDim.x + threadIdx.x;   // [0, BN*HWN/4)
    const int Q = HWN / 4;                            // 16384 float4 per plane
    int b  = t / Q;
    int p4 = t - b * Q;
    const float4* xp = reinterpret_cast<const float4*>(x) + (size_t)b * CN * Q + p4;
    float ax = 0.f, ay = 0.f, az = 0.f, aw = 0.f;
#pragma unroll 8
    for (int c = 0; c < CN; ++c) {
        float4 v = __ldg(xp + (size_t)c * Q);
        ax += v.x; ay += v.y; az += v.z; aw += v.w;
    }
    reinterpret_cast<float4*>(g_cs)[t] = make_float4(ax, ay, az, aw);
}

// ---------------------------------------------------------------------------
// 2) avg_pool2d(k=2, s=1, p=1, count_include_pad=True) on cs -> xs [8,257,257]
//    xs[i,j] = 0.25 * sum of cs over rows {i-1,i}, cols {j-1,j} (zero padded)
// ---------------------------------------------------------------------------
__global__ void k_pool() {
    int t = blockIdx.x * blockDim.x + threadIdx.x;
    if (t >= BN * NPIX) return;
    int b = t / NPIX;
    int p = t - b * NPIX;
    int i = p / WP;
    int j = p - i * WP;
    const float* cs = g_cs + (size_t)b * HWN;

    float s = 0.f;
    int r0 = i - 1, r1 = i, c0 = j - 1, c1 = j;
    bool vr0 = (unsigned)r0 < (unsigned)HN, vr1 = (unsigned)r1 < (unsigned)HN;
    bool vc0 = (unsigned)c0 < (unsigned)WN, vc1 = (unsigned)c1 < (unsigned)WN;
    if (vr0) {
        const float* row = cs + r0 * WN;
        if (vc0) s += row[c0];
        if (vc1) s += row[c1];
    }
    if (vr1) {
        const float* row = cs + r1 * WN;
        if (vc0) s += row[c0];
        if (vc1) s += row[c1];
    }
    g_xs[t] = s * 0.25f;
}

// ---------------------------------------------------------------------------
// 3) 16-tap stencil (the 8 shift-pair features x conv_w) + bias, plus
//    deterministic per-block partial sums for LayerNorm.
//    Grid: (NBLK, BN); 256 threads x 4 pixels.
// ---------------------------------------------------------------------------
__global__ void k_feat(const float* __restrict__ cw, const float* __restrict__ cb) {
    __shared__ float w[8];
    __shared__ float red[256];
    const int tid = threadIdx.x;
    const int b   = blockIdx.y;
    if (tid < 8) w[tid] = cw[tid];
    __syncthreads();
    const float bias = __ldg(cb);

    const float* __restrict__ xs = g_xs + (size_t)b * NPIX;
    float*       __restrict__ y  = g_y  + (size_t)b * NPIX;

    float lsum = 0.f, lsq = 0.f;
#pragma unroll
    for (int k = 0; k < 4; ++k) {
        int p = blockIdx.x * 1024 + k * 256 + tid;
        if (p < NPIX) {
            int h  = p / WP;
            int wi = p - h * WP;
            auto tap = [&](int dr, int dc) -> float {
                int r = h + dr, c = wi + dc;
                if ((unsigned)r < (unsigned)HP && (unsigned)c < (unsigned)WP)
                    return xs[r * WP + c];
                return 0.f;
            };
            float v = bias;
            v += w[0] * (tap( 2,  2) - tap(-2, -2));
            v += w[1] * (tap( 2,  1) - tap(-2, -1));
            v += w[2] * (tap( 2,  0) - tap(-2,  0));
            v += w[3] * (tap( 2, -1) - tap(-2,  1));
            v += w[4] * (tap( 2, -2) - tap(-2,  2));
            v += w[5] * (tap( 1, -2) - tap(-1,  2));
            v += w[6] * (tap( 0, -2) - tap( 0,  2));
            v += w[7] * (tap(-1, -2) - tap( 1,  2));
            y[p] = v;
            lsum += v;
            lsq  += v * v;
        }
    }

    // deterministic block tree reductions
    red[tid] = lsum; __syncthreads();
#pragma unroll
    for (int s = 128; s > 0; s >>= 1) {
        if (tid < s) red[tid] += red[tid + s];
        __syncthreads();
    }
    if (tid == 0) g_part[(b * NBLK + blockIdx.x) * 2 + 0] = red[0];
    __syncthreads();

    red[tid] = lsq; __syncthreads();
#pragma unroll
    for (int s = 128; s > 0; s >>= 1) {
        if (tid < s) red[tid] += red[tid + s];
        __syncthreads();
    }
    if (tid == 0) g_part[(b * NBLK + blockIdx.x) * 2 + 1] = red[0];
}

// ---------------------------------------------------------------------------
// 4) Finalize per-image mean / inv_std.  One block per image.
// ---------------------------------------------------------------------------
__global__ void k_stats() {
    const int b = blockIdx.x;
    const int tid = threadIdx.x;
    __shared__ float s1[128], s2[128];
    float a = 0.f, q = 0.f;
    for (int i = tid; i < NBLK; i += 128) {
        a += g_part[(b * NBLK + i) * 2 + 0];
        q += g_part[(b * NBLK + i) * 2 + 1];
    }
    s1[tid] = a; s2[tid] = q; __syncthreads();
#pragma unroll
    for (int s = 64; s > 0; s >>= 1) {
        if (tid < s) { s1[tid] += s1[tid + s]; s2[tid] += s2[tid + s]; }
        __syncthreads();
    }
    if (tid == 0) {
        float inv_n = 1.0f / (float)NPIX;
        float mean = s1[0] * inv_n;
        float var  = s2[0] * inv_n - mean * mean;
        g_stats[b * 2 + 0] = mean;
        g_stats[b * 2 + 1] = rsqrtf(var + LN_EPS);
    }
}

// ---------------------------------------------------------------------------
// 5) Normalize + LeakyReLU -> d_out  [8,1,257,257]
// ---------------------------------------------------------------------------
__global__ void k_norm(float* __restrict__ out) {
    int t = blockIdx.x * blockDim.x + threadIdx.x;
    if (t >= BN * NPIX) return;
    int b = t / NPIX;
    float v = (g_y[t] - g_stats[b * 2 + 0]) * g_stats[b * 2 + 1];
    out[t] = v >= 0.f ? v : NEG_SLOPE * v;
}

// ---------------------------------------------------------------------------

extern "C" void kernel_launch(void* const* d_in, const int* in_sizes, int n_in,
                              void* d_out, int out_size) {
    const float* x  = (const float*)d_in[0];   // [8,64,256,256]
    const float* cw = (const float*)d_in[1];   // [1,8]
    const float* cb = (const float*)d_in[2];   // [1]
    float* out = (float*)d_out;                // [8,1,257,257]

    (void)in_sizes; (void)n_in; (void)out_size;

    // 1) channel sum: BN*HWN/4 = 131072 threads
    k_chansum<<<(BN * HWN / 4) / 256, 256>>>(x);

    // 2) pool
    int n_pool = BN * NPIX;
    k_pool<<<(n_pool + 255) / 256, 256>>>();

    // 3) stencil + partials
    dim3 gfeat(NBLK, BN);
    k_feat<<<gfeat, 256>>>(cw, cb);

    // 4) stats
    k_stats<<<BN, 128>>>();

    // 5) normalize + leaky relu
    k_norm<<<(n_pool + 255) / 256, 256>>>(out);
}